// round 1
// baseline (speedup 1.0000x reference)
#include <cuda_runtime.h>
#include <math.h>

// Problem constants
#define TT 1024   // tokens
#define HH 1024   // hidden
#define FF 4096   // ffn dim
#define EE 8      // experts

// GEMM tiling
#define BM 64
#define BN 64
#define BK 16

// ---------------- scratch (static device allocations; no runtime alloc) ----
__device__ int   g_cnt[EE];                 // tokens per expert
__device__ int   g_list[EE][TT];            // packed: token*2 + slot
__device__ float g_rw[TT][2];               // routing weights (top-2 probs)
__device__ float g_gu[2][TT][FF];           // gelu(gate)*up per slot  (32 MB)
__device__ float g_dn[2][TT][HH];           // scaled down-proj per slot (8 MB)

// ---------------------------------------------------------------- init ----
__global__ void k_init() {
    if (threadIdx.x < EE) g_cnt[threadIdx.x] = 0;
}

// -------------------------------------------------------------- router ----
// One block per token, 128 threads. Computes logits (written raw to output),
// softmax, top-2 (lowest-index tie-break like jax top_k), appends token to
// the two selected experts' lists.
__global__ void k_router(const float* __restrict__ x,
                         const float* __restrict__ wgate,
                         float* __restrict__ logits_out) {
    int t   = blockIdx.x;
    int tid = threadIdx.x;

    float acc[EE];
#pragma unroll
    for (int e = 0; e < EE; e++) acc[e] = 0.f;

    const float* xr = x + (size_t)t * HH;
    for (int h = tid; h < HH; h += 128) {
        float xv = xr[h];
        const float4* wr = (const float4*)(wgate + (size_t)h * EE);
        float4 w0 = wr[0], w1 = wr[1];
        acc[0] += xv * w0.x; acc[1] += xv * w0.y;
        acc[2] += xv * w0.z; acc[3] += xv * w0.w;
        acc[4] += xv * w1.x; acc[5] += xv * w1.y;
        acc[6] += xv * w1.z; acc[7] += xv * w1.w;
    }

    __shared__ float red[4][EE];
    int lane = tid & 31, warp = tid >> 5;
#pragma unroll
    for (int e = 0; e < EE; e++) {
        float v = acc[e];
#pragma unroll
        for (int o = 16; o > 0; o >>= 1) v += __shfl_down_sync(0xffffffffu, v, o);
        if (lane == 0) red[warp][e] = v;
    }
    __syncthreads();

    if (tid == 0) {
        float lg[EE];
        float mx = -1e30f;
#pragma unroll
        for (int e = 0; e < EE; e++) {
            lg[e] = red[0][e] + red[1][e] + red[2][e] + red[3][e];
            logits_out[(size_t)t * EE + e] = lg[e];
            mx = fmaxf(mx, lg[e]);
        }
        float p[EE], s = 0.f;
#pragma unroll
        for (int e = 0; e < EE; e++) { p[e] = expf(lg[e] - mx); s += p[e]; }
        float inv = 1.f / s;
#pragma unroll
        for (int e = 0; e < EE; e++) p[e] *= inv;

        int i1 = 0;
#pragma unroll
        for (int e = 1; e < EE; e++) if (p[e] > p[i1]) i1 = e;
        int i2 = (i1 == 0) ? 1 : 0;
#pragma unroll
        for (int e = 0; e < EE; e++)
            if (e != i1 && p[e] > p[i2]) i2 = e;

        g_rw[t][0] = p[i1];
        g_rw[t][1] = p[i2];
        int q0 = atomicAdd(&g_cnt[i1], 1);
        g_list[i1][q0] = t * 2 + 0;
        int q1 = atomicAdd(&g_cnt[i2], 1);
        g_list[i2][q1] = t * 2 + 1;
    }
}

// ------------------------------------------------ gate/up GEMM + GELU -----
// Per expert e: C[cnt, F] = X_gathered[cnt, H] @ Wg[e]  (and same with Wv),
// fused into gu = gelu_exact(gate) * up, scattered to g_gu[slot][token][f].
// 64x64 tile, 256 threads, 4x4 microtile (x2 outputs).
__global__ __launch_bounds__(256, 3)
void k_gateup(const float* __restrict__ x,
              const float* __restrict__ wg_all,
              const float* __restrict__ wv_all) {
    int e   = blockIdx.z;
    int cnt = g_cnt[e];
    int m0  = blockIdx.y * BM;
    if (m0 >= cnt) return;
    int n0  = blockIdx.x * BN;

    const float* Bg = wg_all + (size_t)e * HH * FF;
    const float* Bv = wv_all + (size_t)e * HH * FF;

    __shared__ float As[BK][BM + 4];   // A transposed: [k][m]
    __shared__ float Sg[BK][BN];
    __shared__ float Sv[BK][BN];

    int tid = threadIdx.x;
    // A loader mapping: 64 rows x 4 float4 chunks along k
    int lm = tid >> 2, kq = tid & 3;
    int row = m0 + lm;
    const float* arow = nullptr;
    if (row < cnt) {
        int tok = g_list[e][row] >> 1;
        arow = x + (size_t)tok * HH;
    }
    // B loader mapping: 16 k-rows x 16 float4 chunks along n
    int bk = tid >> 4, bn4 = (tid & 15) * 4;
    // compute mapping: 16x16 thread grid
    int ty = tid >> 4, tx = tid & 15;

    float ag[4][4], av_[4][4];
#pragma unroll
    for (int i = 0; i < 4; i++)
#pragma unroll
        for (int j = 0; j < 4; j++) { ag[i][j] = 0.f; av_[i][j] = 0.f; }

    for (int k0 = 0; k0 < HH; k0 += BK) {
        float4 a4 = make_float4(0.f, 0.f, 0.f, 0.f);
        if (arow) a4 = *(const float4*)(arow + k0 + kq * 4);
        As[kq * 4 + 0][lm] = a4.x;
        As[kq * 4 + 1][lm] = a4.y;
        As[kq * 4 + 2][lm] = a4.z;
        As[kq * 4 + 3][lm] = a4.w;

        *(float4*)&Sg[bk][bn4] = *(const float4*)(Bg + (size_t)(k0 + bk) * FF + n0 + bn4);
        *(float4*)&Sv[bk][bn4] = *(const float4*)(Bv + (size_t)(k0 + bk) * FF + n0 + bn4);
        __syncthreads();

#pragma unroll
        for (int k = 0; k < BK; k++) {
            float4 a  = *(const float4*)&As[k][ty * 4];
            float4 bg = *(const float4*)&Sg[k][tx * 4];
            float4 bv = *(const float4*)&Sv[k][tx * 4];
            float am[4]  = {a.x,  a.y,  a.z,  a.w};
            float bgv[4] = {bg.x, bg.y, bg.z, bg.w};
            float bvv[4] = {bv.x, bv.y, bv.z, bv.w};
#pragma unroll
            for (int i = 0; i < 4; i++)
#pragma unroll
                for (int j = 0; j < 4; j++) {
                    ag[i][j]  += am[i] * bgv[j];
                    av_[i][j] += am[i] * bvv[j];
                }
        }
        __syncthreads();
    }

#pragma unroll
    for (int i = 0; i < 4; i++) {
        int r = m0 + ty * 4 + i;
        if (r < cnt) {
            int ts = g_list[e][r];
            int t = ts >> 1, slot = ts & 1;
            float* gout = &g_gu[slot][t][n0 + tx * 4];
#pragma unroll
            for (int j = 0; j < 4; j++) {
                float g  = ag[i][j];
                float gl = 0.5f * g * (1.f + erff(g * 0.70710678118654752f));
                gout[j]  = gl * av_[i][j];
            }
        }
    }
}

// -------------------------------------------------------- down GEMM -------
// Per expert e: D[cnt, H] = GU_gathered[cnt, F] @ W1[e], scaled by routing
// weight and scattered to g_dn[slot][token][h].
__global__ __launch_bounds__(256, 3)
void k_down(const float* __restrict__ w1_all) {
    int e   = blockIdx.z;
    int cnt = g_cnt[e];
    int m0  = blockIdx.y * BM;
    if (m0 >= cnt) return;
    int n0  = blockIdx.x * BN;

    const float* B = w1_all + (size_t)e * FF * HH;

    __shared__ float As[BK][BM + 4];
    __shared__ float Sb[BK][BN];

    int tid = threadIdx.x;
    int lm = tid >> 2, kq = tid & 3;
    int row = m0 + lm;
    const float* arow = nullptr;
    if (row < cnt) {
        int ts = g_list[e][row];
        arow = &g_gu[ts & 1][ts >> 1][0];
    }
    int bk = tid >> 4, bn4 = (tid & 15) * 4;
    int ty = tid >> 4, tx = tid & 15;

    float acc[4][4];
#pragma unroll
    for (int i = 0; i < 4; i++)
#pragma unroll
        for (int j = 0; j < 4; j++) acc[i][j] = 0.f;

    for (int k0 = 0; k0 < FF; k0 += BK) {
        float4 a4 = make_float4(0.f, 0.f, 0.f, 0.f);
        if (arow) a4 = *(const float4*)(arow + k0 + kq * 4);
        As[kq * 4 + 0][lm] = a4.x;
        As[kq * 4 + 1][lm] = a4.y;
        As[kq * 4 + 2][lm] = a4.z;
        As[kq * 4 + 3][lm] = a4.w;

        *(float4*)&Sb[bk][bn4] = *(const float4*)(B + (size_t)(k0 + bk) * HH + n0 + bn4);
        __syncthreads();

#pragma unroll
        for (int k = 0; k < BK; k++) {
            float4 a = *(const float4*)&As[k][ty * 4];
            float4 b = *(const float4*)&Sb[k][tx * 4];
            float am[4] = {a.x, a.y, a.z, a.w};
            float bv[4] = {b.x, b.y, b.z, b.w};
#pragma unroll
            for (int i = 0; i < 4; i++)
#pragma unroll
                for (int j = 0; j < 4; j++)
                    acc[i][j] += am[i] * bv[j];
        }
        __syncthreads();
    }

#pragma unroll
    for (int i = 0; i < 4; i++) {
        int r = m0 + ty * 4 + i;
        if (r < cnt) {
            int ts = g_list[e][r];
            int t = ts >> 1, slot = ts & 1;
            float w = g_rw[t][slot];
            float* o = &g_dn[slot][t][n0 + tx * 4];
#pragma unroll
            for (int j = 0; j < 4; j++) o[j] = w * acc[i][j];
        }
    }
}

// ------------------------------------------------------------ combine -----
__global__ void k_combine(float* __restrict__ out) {
    int i = blockIdx.x * blockDim.x + threadIdx.x;   // over T*H/4
    const float4* a = (const float4*)&g_dn[0][0][0];
    const float4* b = (const float4*)&g_dn[1][0][0];
    float4 u = a[i], v = b[i];
    ((float4*)out)[i] = make_float4(u.x + v.x, u.y + v.y, u.z + v.z, u.w + v.w);
}

// ------------------------------------------------------------- launch -----
extern "C" void kernel_launch(void* const* d_in, const int* in_sizes, int n_in,
                              void* d_out, int out_size) {
    const float* x      = (const float*)d_in[0];  // [1,1024,1024]
    const float* wgate  = (const float*)d_in[1];  // [1024, 8]
    const float* wg     = (const float*)d_in[2];  // [8,1024,4096]
    const float* wv     = (const float*)d_in[3];  // [8,1024,4096]
    const float* w1     = (const float*)d_in[4];  // [8,4096,1024]
    float* out = (float*)d_out;                   // out[1,1024,1024] ++ logits[1024,8]

    k_init<<<1, 32>>>();
    k_router<<<TT, 128>>>(x, wgate, out + (size_t)TT * HH);
    k_gateup<<<dim3(FF / BN, TT / BM, EE), 256>>>(x, wg, wv);
    k_down<<<dim3(HH / BN, TT / BM, EE), 256>>>(w1);
    k_combine<<<(TT * HH / 4) / 256, 256>>>(out);
}

// round 6
// speedup vs baseline: 1.5563x; 1.5563x over previous
#include <cuda_runtime.h>
#include <cuda_bf16.h>
#include <math.h>
#include <stdint.h>

#define TT 1024
#define HH 1024
#define FF 4096
#define EE 8

// ===================== MMA helper ===========================================
__device__ __forceinline__ void mma_bf16(float* c, const uint32_t* a, const uint32_t* b) {
    asm volatile(
        "mma.sync.aligned.m16n8k16.row.col.f32.bf16.bf16.f32 "
        "{%0,%1,%2,%3}, {%4,%5,%6,%7}, {%8,%9}, {%0,%1,%2,%3};"
        : "+f"(c[0]), "+f"(c[1]), "+f"(c[2]), "+f"(c[3])
        : "r"(a[0]), "r"(a[1]), "r"(a[2]), "r"(a[3]), "r"(b[0]), "r"(b[1]));
}

// swizzled byte offset within a 32B-row tile: half = 16B chunk index (0/1)
__device__ __forceinline__ int aoff(int row, int half) {
    return row * 32 + ((half << 4) ^ ((row & 4) << 2));
}

__device__ __forceinline__ uint32_t pack_bf16(float x, float y) {
    __nv_bfloat162 p;
    p.x = __float2bfloat16(x);
    p.y = __float2bfloat16(y);
    return *reinterpret_cast<uint32_t*>(&p);
}

// ===================== scratch ==============================================
__device__ int   g_cnt[EE];
__device__ int   g_off[EE];
__device__ int   g_list[EE][TT];
__device__ float g_rw[TT][2];

__device__ __nv_bfloat16 g_wghi[(size_t)EE * FF * HH];   // [e][f][h]
__device__ __nv_bfloat16 g_wglo[(size_t)EE * FF * HH];
__device__ __nv_bfloat16 g_wvhi[(size_t)EE * FF * HH];
__device__ __nv_bfloat16 g_wvlo[(size_t)EE * FF * HH];
__device__ __nv_bfloat16 g_w1hi[(size_t)EE * HH * FF];   // [e][h][f]
__device__ __nv_bfloat16 g_w1lo[(size_t)EE * HH * FF];
__device__ __nv_bfloat16 g_guhi[(size_t)2 * TT * FF];    // [grow][f]
__device__ __nv_bfloat16 g_gulo[(size_t)2 * TT * FF];
__device__ float g_dn[2][TT][HH];

// ===================== small kernels ========================================
__global__ void k_init() { if (threadIdx.x < EE) g_cnt[threadIdx.x] = 0; }

__global__ void k_router(const float* __restrict__ x,
                         const float* __restrict__ wgate,
                         float* __restrict__ logits_out) {
    int t = blockIdx.x, tid = threadIdx.x;
    float acc[EE];
#pragma unroll
    for (int e = 0; e < EE; e++) acc[e] = 0.f;
    const float* xr = x + (size_t)t * HH;
    for (int h = tid; h < HH; h += 128) {
        float xv = xr[h];
        const float4* wr = (const float4*)(wgate + (size_t)h * EE);
        float4 w0 = wr[0], w1 = wr[1];
        acc[0] += xv * w0.x; acc[1] += xv * w0.y;
        acc[2] += xv * w0.z; acc[3] += xv * w0.w;
        acc[4] += xv * w1.x; acc[5] += xv * w1.y;
        acc[6] += xv * w1.z; acc[7] += xv * w1.w;
    }
    __shared__ float red[4][EE];
    int lane = tid & 31, warp = tid >> 5;
#pragma unroll
    for (int e = 0; e < EE; e++) {
        float v = acc[e];
#pragma unroll
        for (int o = 16; o > 0; o >>= 1) v += __shfl_down_sync(0xffffffffu, v, o);
        if (lane == 0) red[warp][e] = v;
    }
    __syncthreads();
    if (tid == 0) {
        float lg[EE], mx = -1e30f;
#pragma unroll
        for (int e = 0; e < EE; e++) {
            lg[e] = red[0][e] + red[1][e] + red[2][e] + red[3][e];
            logits_out[(size_t)t * EE + e] = lg[e];
            mx = fmaxf(mx, lg[e]);
        }
        float p[EE], s = 0.f;
#pragma unroll
        for (int e = 0; e < EE; e++) { p[e] = expf(lg[e] - mx); s += p[e]; }
        float inv = 1.f / s;
#pragma unroll
        for (int e = 0; e < EE; e++) p[e] *= inv;
        int i1 = 0;
#pragma unroll
        for (int e = 1; e < EE; e++) if (p[e] > p[i1]) i1 = e;
        int i2 = (i1 == 0) ? 1 : 0;
#pragma unroll
        for (int e = 0; e < EE; e++) if (e != i1 && p[e] > p[i2]) i2 = e;
        g_rw[t][0] = p[i1];
        g_rw[t][1] = p[i2];
        int q0 = atomicAdd(&g_cnt[i1], 1); g_list[i1][q0] = t * 2 + 0;
        int q1 = atomicAdd(&g_cnt[i2], 1); g_list[i2][q1] = t * 2 + 1;
    }
}

__global__ void k_prefix() {
    if (threadIdx.x == 0) {
        int s = 0;
        for (int e = 0; e < EE; e++) { g_off[e] = s; s += g_cnt[e]; }
    }
}

// transpose+split: src[e][k][n] fp32 -> hi/lo[e][n][k] bf16.
// Destination selected INSIDE device code (host code must never take the
// address of a __device__ symbol).
template <int W>
__global__ void k_convw(const float* __restrict__ src, int K, int N) {
    __nv_bfloat16* hi = (W == 0) ? g_wghi : (W == 1) ? g_wvhi : g_w1hi;
    __nv_bfloat16* lo = (W == 0) ? g_wglo : (W == 1) ? g_wvlo : g_w1lo;
    __shared__ float tile[32][33];
    int e = blockIdx.z;
    int n0 = blockIdx.x * 32, k0 = blockIdx.y * 32;
    int tx = threadIdx.x, ty = threadIdx.y;
    const float* s = src + ((size_t)e * K + k0) * N + n0;
#pragma unroll
    for (int i = 0; i < 32; i += 8) tile[ty + i][tx] = s[(size_t)(i + ty) * N + tx];
    __syncthreads();
    __nv_bfloat16* ho = hi + ((size_t)e * N + n0) * K + k0;
    __nv_bfloat16* lq = lo + ((size_t)e * N + n0) * K + k0;
#pragma unroll
    for (int i = 0; i < 32; i += 8) {
        float v = tile[tx][ty + i];
        __nv_bfloat16 h = __float2bfloat16(v);
        ho[(size_t)(ty + i) * K + tx] = h;
        lq[(size_t)(ty + i) * K + tx] = __float2bfloat16(v - __bfloat162float(h));
    }
}

// ===================== GEMM1: gate/up =======================================
// Block: M=64 gathered rows, N=128 F-cols (gate AND up). K-chunk = 16.
// Stage 20KB, double-buffered = 40KB dynamic smem.
#define G1_AHI 0
#define G1_ALO 2048
#define G1_GH  4096
#define G1_GL  8192
#define G1_VH  12288
#define G1_VL  16384
#define G1_STAGE 20480
#define G1_SMEM (2 * G1_STAGE)

__global__ void __launch_bounds__(256)
k_gemm1(const float* __restrict__ x) {
    int e = blockIdx.z;
    int cnt = g_cnt[e];
    int m0 = blockIdx.y * 64;
    if (m0 >= cnt) return;
    int n0 = blockIdx.x * 128;

    extern __shared__ char smem[];
    int tid = threadIdx.x;
    int lane = tid & 31, wid = tid >> 5;
    int wm = wid & 1, wn = wid >> 1;
    int qr = lane >> 2;
    int qc = (lane & 3) << 2;

    __shared__ int s_tok[64];
    if (tid < 64) {
        int r = m0 + tid;
        s_tok[tid] = (r < cnt) ? (g_list[e][r] >> 1) : -1;
    }
    __syncthreads();

    const float4* x4 = (const float4*)x;
    const uint4* pgh = (const uint4*)g_wghi;
    const uint4* pgl = (const uint4*)g_wglo;
    const uint4* pvh = (const uint4*)g_wvhi;
    const uint4* pvl = (const uint4*)g_wvlo;
    size_t bbase = ((size_t)e * FF + n0) * (HH / 8);

    int arow = tid >> 2, aq = tid & 3;
    int aso = arow * 32 + (((aq >> 1) << 4) ^ ((arow & 4) << 2)) + (aq & 1) * 8;
    int atok = s_tok[arow];
    int brow = tid >> 1, bcb = tid & 1;
    int bso = brow * 32 + ((bcb << 4) ^ ((brow & 4) << 2));

    auto load_chunk = [&](int j, int st) {
        char* base = smem + st * G1_STAGE;
        float4 v = make_float4(0.f, 0.f, 0.f, 0.f);
        if (atok >= 0) v = x4[(size_t)atok * (HH / 4) + j * 4 + aq];
        uint32_t h0 = pack_bf16(v.x, v.y), h1 = pack_bf16(v.z, v.w);
        float rx = v.x - __bfloat162float(__float2bfloat16(v.x));
        float ry = v.y - __bfloat162float(__float2bfloat16(v.y));
        float rz = v.z - __bfloat162float(__float2bfloat16(v.z));
        float rw = v.w - __bfloat162float(__float2bfloat16(v.w));
        uint32_t l0 = pack_bf16(rx, ry), l1 = pack_bf16(rz, rw);
        *(uint2*)(base + G1_AHI + aso) = make_uint2(h0, h1);
        *(uint2*)(base + G1_ALO + aso) = make_uint2(l0, l1);
        size_t gi = bbase + (size_t)brow * (HH / 8) + j * 2 + bcb;
        *(uint4*)(base + G1_GH + bso) = pgh[gi];
        *(uint4*)(base + G1_GL + bso) = pgl[gi];
        *(uint4*)(base + G1_VH + bso) = pvh[gi];
        *(uint4*)(base + G1_VL + bso) = pvl[gi];
    };

    float accg[2][4][4], accu[2][4][4];
#pragma unroll
    for (int i = 0; i < 2; i++)
#pragma unroll
        for (int j = 0; j < 4; j++)
#pragma unroll
            for (int q = 0; q < 4; q++) { accg[i][j][q] = 0.f; accu[i][j][q] = 0.f; }

    auto compute_chunk = [&](int st) {
        const char* base = smem + st * G1_STAGE;
        uint32_t ah[2][4], al[2][4];
#pragma unroll
        for (int i = 0; i < 2; i++) {
            int r = wm * 32 + i * 16 + qr;
            const char* pH = base + G1_AHI;
            const char* pL = base + G1_ALO;
            ah[i][0] = *(const uint32_t*)(pH + aoff(r, 0) + qc);
            ah[i][1] = *(const uint32_t*)(pH + aoff(r + 8, 0) + qc);
            ah[i][2] = *(const uint32_t*)(pH + aoff(r, 1) + qc);
            ah[i][3] = *(const uint32_t*)(pH + aoff(r + 8, 1) + qc);
            al[i][0] = *(const uint32_t*)(pL + aoff(r, 0) + qc);
            al[i][1] = *(const uint32_t*)(pL + aoff(r + 8, 0) + qc);
            al[i][2] = *(const uint32_t*)(pL + aoff(r, 1) + qc);
            al[i][3] = *(const uint32_t*)(pL + aoff(r + 8, 1) + qc);
        }
#pragma unroll
        for (int j = 0; j < 4; j++) {
            int rb = wn * 32 + j * 8 + qr;
            uint32_t bgh[2], bgl[2], bvh[2], bvl[2];
            bgh[0] = *(const uint32_t*)(base + G1_GH + aoff(rb, 0) + qc);
            bgh[1] = *(const uint32_t*)(base + G1_GH + aoff(rb, 1) + qc);
            bgl[0] = *(const uint32_t*)(base + G1_GL + aoff(rb, 0) + qc);
            bgl[1] = *(const uint32_t*)(base + G1_GL + aoff(rb, 1) + qc);
            bvh[0] = *(const uint32_t*)(base + G1_VH + aoff(rb, 0) + qc);
            bvh[1] = *(const uint32_t*)(base + G1_VH + aoff(rb, 1) + qc);
            bvl[0] = *(const uint32_t*)(base + G1_VL + aoff(rb, 0) + qc);
            bvl[1] = *(const uint32_t*)(base + G1_VL + aoff(rb, 1) + qc);
#pragma unroll
            for (int i = 0; i < 2; i++) {
                mma_bf16(accg[i][j], ah[i], bgh);
                mma_bf16(accg[i][j], al[i], bgh);
                mma_bf16(accg[i][j], ah[i], bgl);
                mma_bf16(accu[i][j], ah[i], bvh);
                mma_bf16(accu[i][j], al[i], bvh);
                mma_bf16(accu[i][j], ah[i], bvl);
            }
        }
    };

    load_chunk(0, 0);
    __syncthreads();
#pragma unroll 1
    for (int j = 0; j < 64; j++) {
        if (j + 1 < 64) load_chunk(j + 1, (j + 1) & 1);
        compute_chunk(j & 1);
        __syncthreads();
    }

    int c2 = (lane & 3) << 1;
#pragma unroll
    for (int i = 0; i < 2; i++) {
        int er0 = m0 + wm * 32 + i * 16 + qr;
        int er1 = er0 + 8;
        int gr0 = g_off[e] + er0, gr1 = g_off[e] + er1;
#pragma unroll
        for (int j = 0; j < 4; j++) {
            int col = n0 + wn * 32 + j * 8 + c2;
#pragma unroll
            for (int h = 0; h < 2; h++) {
                int er = h ? er1 : er0;
                if (er >= cnt) continue;
                int grow = h ? gr1 : gr0;
                float gx = accg[i][j][h * 2 + 0], gy = accg[i][j][h * 2 + 1];
                float ux = accu[i][j][h * 2 + 0], uy = accu[i][j][h * 2 + 1];
                float g0 = 0.5f * gx * (1.f + erff(gx * 0.70710678118654752f)) * ux;
                float g1 = 0.5f * gy * (1.f + erff(gy * 0.70710678118654752f)) * uy;
                __nv_bfloat16 h0 = __float2bfloat16(g0);
                __nv_bfloat16 h1 = __float2bfloat16(g1);
                __nv_bfloat162 hp; hp.x = h0; hp.y = h1;
                __nv_bfloat162 lp;
                lp.x = __float2bfloat16(g0 - __bfloat162float(h0));
                lp.y = __float2bfloat16(g1 - __bfloat162float(h1));
                size_t bo = (size_t)grow * FF + col;
                *reinterpret_cast<__nv_bfloat162*>(&g_guhi[bo]) = hp;
                *reinterpret_cast<__nv_bfloat162*>(&g_gulo[bo]) = lp;
            }
        }
    }
}

// ===================== GEMM2: down ==========================================
#define G2_AHI 0
#define G2_ALO 2048
#define G2_BH  4096
#define G2_BL  8192
#define G2_STAGE 12288
#define G2_SMEM (2 * G2_STAGE)

__global__ void __launch_bounds__(256)
k_gemm2() {
    int e = blockIdx.z;
    int cnt = g_cnt[e];
    int m0 = blockIdx.y * 64;
    if (m0 >= cnt) return;
    int n0 = blockIdx.x * 128;

    extern __shared__ char smem[];
    int tid = threadIdx.x;
    int lane = tid & 31, wid = tid >> 5;
    int wm = wid & 1, wn = wid >> 1;
    int qr = lane >> 2;
    int qc = (lane & 3) << 2;

    __shared__ int s_grow[64];
    if (tid < 64) {
        int r = m0 + tid;
        s_grow[tid] = (r < cnt) ? (g_off[e] + r) : -1;
    }
    __syncthreads();

    const uint4* ahi4 = (const uint4*)g_guhi;
    const uint4* alo4 = (const uint4*)g_gulo;
    const uint4* pbh  = (const uint4*)g_w1hi;
    const uint4* pbl  = (const uint4*)g_w1lo;
    size_t bbase = ((size_t)e * HH + n0) * (FF / 8);
    const uint4 z4 = make_uint4(0, 0, 0, 0);

    int am = tid >> 7, arem = tid & 127, arow = arem >> 1, acb = arem & 1;
    int aso = arow * 32 + ((acb << 4) ^ ((arow & 4) << 2)) + (am ? G2_ALO : G2_AHI);
    int agrow = s_grow[arow];
    int brow = tid >> 1, bcb = tid & 1;
    int bso = brow * 32 + ((bcb << 4) ^ ((brow & 4) << 2));

    auto load_chunk = [&](int j, int st) {
        char* base = smem + st * G2_STAGE;
        uint4 va = z4;
        if (agrow >= 0) {
            size_t gi = (size_t)agrow * (FF / 8) + j * 2 + acb;
            va = am ? alo4[gi] : ahi4[gi];
        }
        *(uint4*)(base + aso) = va;
        size_t gi = bbase + (size_t)brow * (FF / 8) + j * 2 + bcb;
        *(uint4*)(base + G2_BH + bso) = pbh[gi];
        *(uint4*)(base + G2_BL + bso) = pbl[gi];
    };

    float acc[2][4][4];
#pragma unroll
    for (int i = 0; i < 2; i++)
#pragma unroll
        for (int j = 0; j < 4; j++)
#pragma unroll
            for (int q = 0; q < 4; q++) acc[i][j][q] = 0.f;

    auto compute_chunk = [&](int st) {
        const char* base = smem + st * G2_STAGE;
        uint32_t ah[2][4], al[2][4];
#pragma unroll
        for (int i = 0; i < 2; i++) {
            int r = wm * 32 + i * 16 + qr;
            const char* pH = base + G2_AHI;
            const char* pL = base + G2_ALO;
            ah[i][0] = *(const uint32_t*)(pH + aoff(r, 0) + qc);
            ah[i][1] = *(const uint32_t*)(pH + aoff(r + 8, 0) + qc);
            ah[i][2] = *(const uint32_t*)(pH + aoff(r, 1) + qc);
            ah[i][3] = *(const uint32_t*)(pH + aoff(r + 8, 1) + qc);
            al[i][0] = *(const uint32_t*)(pL + aoff(r, 0) + qc);
            al[i][1] = *(const uint32_t*)(pL + aoff(r + 8, 0) + qc);
            al[i][2] = *(const uint32_t*)(pL + aoff(r, 1) + qc);
            al[i][3] = *(const uint32_t*)(pL + aoff(r + 8, 1) + qc);
        }
#pragma unroll
        for (int j = 0; j < 4; j++) {
            int rb = wn * 32 + j * 8 + qr;
            uint32_t bh[2], bl[2];
            bh[0] = *(const uint32_t*)(base + G2_BH + aoff(rb, 0) + qc);
            bh[1] = *(const uint32_t*)(base + G2_BH + aoff(rb, 1) + qc);
            bl[0] = *(const uint32_t*)(base + G2_BL + aoff(rb, 0) + qc);
            bl[1] = *(const uint32_t*)(base + G2_BL + aoff(rb, 1) + qc);
#pragma unroll
            for (int i = 0; i < 2; i++) {
                mma_bf16(acc[i][j], ah[i], bh);
                mma_bf16(acc[i][j], al[i], bh);
                mma_bf16(acc[i][j], ah[i], bl);
            }
        }
    };

    load_chunk(0, 0);
    __syncthreads();
#pragma unroll 1
    for (int j = 0; j < 256; j++) {
        if (j + 1 < 256) load_chunk(j + 1, (j + 1) & 1);
        compute_chunk(j & 1);
        __syncthreads();
    }

    int c2 = (lane & 3) << 1;
#pragma unroll
    for (int i = 0; i < 2; i++) {
        int er0 = m0 + wm * 32 + i * 16 + qr;
        int er1 = er0 + 8;
        int tok0 = 0, tok1 = 0, sl0 = 0, sl1 = 0; float w0 = 0.f, w1 = 0.f;
        if (er0 < cnt) { int ts = g_list[e][er0]; tok0 = ts >> 1; sl0 = ts & 1; w0 = g_rw[tok0][sl0]; }
        if (er1 < cnt) { int ts = g_list[e][er1]; tok1 = ts >> 1; sl1 = ts & 1; w1 = g_rw[tok1][sl1]; }
#pragma unroll
        for (int j = 0; j < 4; j++) {
            int col = n0 + wn * 32 + j * 8 + c2;
            if (er0 < cnt) {
                float* o = &g_dn[sl0][tok0][col];
                o[0] = w0 * acc[i][j][0];
                o[1] = w0 * acc[i][j][1];
            }
            if (er1 < cnt) {
                float* o = &g_dn[sl1][tok1][col];
                o[0] = w1 * acc[i][j][2];
                o[1] = w1 * acc[i][j][3];
            }
        }
    }
}

// ===================== combine ==============================================
__global__ void k_combine(float* __restrict__ out) {
    int i = blockIdx.x * blockDim.x + threadIdx.x;
    const float4* a = (const float4*)&g_dn[0][0][0];
    const float4* b = (const float4*)&g_dn[1][0][0];
    float4 u = a[i], v = b[i];
    ((float4*)out)[i] = make_float4(u.x + v.x, u.y + v.y, u.z + v.z, u.w + v.w);
}

// ===================== launch ==============================================
extern "C" void kernel_launch(void* const* d_in, const int* in_sizes, int n_in,
                              void* d_out, int out_size) {
    const float* x     = (const float*)d_in[0];
    const float* wgate = (const float*)d_in[1];
    const float* wg    = (const float*)d_in[2];
    const float* wv    = (const float*)d_in[3];
    const float* w1    = (const float*)d_in[4];
    float* out = (float*)d_out;

    k_init<<<1, 32>>>();
    k_router<<<TT, 128>>>(x, wgate, out + (size_t)TT * HH);
    k_prefix<<<1, 32>>>();

    dim3 tconv(32, 8);
    k_convw<0><<<dim3(FF / 32, HH / 32, EE), tconv>>>(wg, HH, FF);
    k_convw<1><<<dim3(FF / 32, HH / 32, EE), tconv>>>(wv, HH, FF);
    k_convw<2><<<dim3(HH / 32, FF / 32, EE), tconv>>>(w1, FF, HH);

    k_gemm1<<<dim3(FF / 128, TT / 64, EE), 256, G1_SMEM>>>(x);
    k_gemm2<<<dim3(HH / 128, TT / 64, EE), 256, G2_SMEM>>>();
    k_combine<<<(TT * HH / 4) / 256, 256>>>(out);
}

// round 8
// speedup vs baseline: 1.7144x; 1.1016x over previous
#include <cuda_runtime.h>
#include <cuda_bf16.h>
#include <math.h>
#include <stdint.h>

#define TT 1024
#define HH 1024
#define FF 4096
#define EE 8

// ===================== helpers ==============================================
__device__ __forceinline__ uint32_t smem_to_u32(const void* p) {
    uint32_t a;
    asm("{ .reg .u64 t; cvta.to.shared.u64 t, %1; cvt.u32.u64 %0, t; }" : "=r"(a) : "l"(p));
    return a;
}

__device__ __forceinline__ void mma_bf16(float* c, const uint32_t* a, const uint32_t* b) {
    asm volatile(
        "mma.sync.aligned.m16n8k16.row.col.f32.bf16.bf16.f32 "
        "{%0,%1,%2,%3}, {%4,%5,%6,%7}, {%8,%9}, {%0,%1,%2,%3};"
        : "+f"(c[0]), "+f"(c[1]), "+f"(c[2]), "+f"(c[3])
        : "r"(a[0]), "r"(a[1]), "r"(a[2]), "r"(a[3]), "r"(b[0]), "r"(b[1]));
}

#define CP_ASYNC16(dst32, srcp) \
    asm volatile("cp.async.cg.shared.global [%0], [%1], 16;" :: "r"(dst32), "l"(srcp))
#define CP_COMMIT() asm volatile("cp.async.commit_group;" ::: "memory")
#define CP_WAIT2()  asm volatile("cp.async.wait_group 2;" ::: "memory")

// swizzled byte offset within a 32B-row tile: half = 16B chunk index (0/1)
__device__ __forceinline__ int aoff(int row, int half) {
    return row * 32 + ((half << 4) ^ ((row & 4) << 2));
}

__device__ __forceinline__ uint32_t pack_bf16(float x, float y) {
    __nv_bfloat162 p;
    p.x = __float2bfloat16(x);
    p.y = __float2bfloat16(y);
    return *reinterpret_cast<uint32_t*>(&p);
}

// ===================== scratch ==============================================
__device__ int   g_cnt[EE];
__device__ int   g_off[EE];
__device__ int   g_list[EE][TT];
__device__ float g_rw[TT][2];

__device__ __nv_bfloat16 g_wghi[(size_t)EE * FF * HH];   // [e][f][h] K-major
__device__ __nv_bfloat16 g_wglo[(size_t)EE * FF * HH];
__device__ __nv_bfloat16 g_wvhi[(size_t)EE * FF * HH];
__device__ __nv_bfloat16 g_wvlo[(size_t)EE * FF * HH];
__device__ __nv_bfloat16 g_w1hi[(size_t)EE * HH * FF];   // [e][h][f] K-major
__device__ __nv_bfloat16 g_w1lo[(size_t)EE * HH * FF];
__device__ __nv_bfloat16 g_guhi[(size_t)(2 * TT + 128) * FF];  // [grow][f] (+pad)
__device__ __nv_bfloat16 g_gulo[(size_t)(2 * TT + 128) * FF];
__device__ float g_dn[2][TT][HH];

// ===================== small kernels ========================================
__global__ void k_init() { if (threadIdx.x < EE) g_cnt[threadIdx.x] = 0; }

__global__ void k_router(const float* __restrict__ x,
                         const float* __restrict__ wgate,
                         float* __restrict__ logits_out) {
    int t = blockIdx.x, tid = threadIdx.x;
    float acc[EE];
#pragma unroll
    for (int e = 0; e < EE; e++) acc[e] = 0.f;
    const float* xr = x + (size_t)t * HH;
    for (int h = tid; h < HH; h += 128) {
        float xv = xr[h];
        const float4* wr = (const float4*)(wgate + (size_t)h * EE);
        float4 w0 = wr[0], w1 = wr[1];
        acc[0] += xv * w0.x; acc[1] += xv * w0.y;
        acc[2] += xv * w0.z; acc[3] += xv * w0.w;
        acc[4] += xv * w1.x; acc[5] += xv * w1.y;
        acc[6] += xv * w1.z; acc[7] += xv * w1.w;
    }
    __shared__ float red[4][EE];
    int lane = tid & 31, warp = tid >> 5;
#pragma unroll
    for (int e = 0; e < EE; e++) {
        float v = acc[e];
#pragma unroll
        for (int o = 16; o > 0; o >>= 1) v += __shfl_down_sync(0xffffffffu, v, o);
        if (lane == 0) red[warp][e] = v;
    }
    __syncthreads();
    if (tid == 0) {
        float lg[EE], mx = -1e30f;
#pragma unroll
        for (int e = 0; e < EE; e++) {
            lg[e] = red[0][e] + red[1][e] + red[2][e] + red[3][e];
            logits_out[(size_t)t * EE + e] = lg[e];
            mx = fmaxf(mx, lg[e]);
        }
        float p[EE], s = 0.f;
#pragma unroll
        for (int e = 0; e < EE; e++) { p[e] = expf(lg[e] - mx); s += p[e]; }
        float inv = 1.f / s;
#pragma unroll
        for (int e = 0; e < EE; e++) p[e] *= inv;
        int i1 = 0;
#pragma unroll
        for (int e = 1; e < EE; e++) if (p[e] > p[i1]) i1 = e;
        int i2 = (i1 == 0) ? 1 : 0;
#pragma unroll
        for (int e = 0; e < EE; e++) if (e != i1 && p[e] > p[i2]) i2 = e;
        g_rw[t][0] = p[i1];
        g_rw[t][1] = p[i2];
        int q0 = atomicAdd(&g_cnt[i1], 1); g_list[i1][q0] = t * 2 + 0;
        int q1 = atomicAdd(&g_cnt[i2], 1); g_list[i2][q1] = t * 2 + 1;
    }
}

__global__ void k_prefix() {
    if (threadIdx.x == 0) {
        int s = 0;
        for (int e = 0; e < EE; e++) { g_off[e] = s; s += g_cnt[e]; }
    }
}

// ===================== weight conversion ====================================
__global__ void __launch_bounds__(256)
k_conv_gv(const float* __restrict__ wg, const float* __restrict__ wv) {
    const int K = HH, N = FF;
    int e = blockIdx.z >> 1, which = blockIdx.z & 1;
    const float* src = which ? wv : wg;
    __nv_bfloat16* hi = which ? g_wvhi : g_wghi;
    __nv_bfloat16* lo = which ? g_wvlo : g_wglo;
    int k0 = blockIdx.y * 64, n0 = blockIdx.x * 32;
    __shared__ float tile[64][33];
    int tid = threadIdx.x;
#pragma unroll
    for (int i = 0; i < 8; i++) {
        int idx = tid + 256 * i;
        int k = idx >> 5, n = idx & 31;
        tile[k][n] = src[((size_t)e * K + k0 + k) * N + n0 + n];
    }
    __syncthreads();
    int w = tid >> 5, l = tid & 31;
#pragma unroll
    for (int m = 0; m < 4; m++) {
        int n = w + 8 * m;
        float a = tile[2 * l][n], b = tile[2 * l + 1][n];
        __nv_bfloat16 ha = __float2bfloat16(a), hb = __float2bfloat16(b);
        __nv_bfloat162 hp; hp.x = ha; hp.y = hb;
        __nv_bfloat162 lp;
        lp.x = __float2bfloat16(a - __bfloat162float(ha));
        lp.y = __float2bfloat16(b - __bfloat162float(hb));
        size_t o = ((size_t)e * N + n0 + n) * K + k0 + 2 * l;
        *(__nv_bfloat162*)&hi[o] = hp;
        *(__nv_bfloat162*)&lo[o] = lp;
    }
}

__global__ void __launch_bounds__(256)
k_conv_w1(const float* __restrict__ w1) {
    const int K = FF, N = HH;
    int e = blockIdx.z;
    int k0 = blockIdx.y * 64, n0 = blockIdx.x * 32;
    __shared__ float tile[64][33];
    int tid = threadIdx.x;
#pragma unroll
    for (int i = 0; i < 8; i++) {
        int idx = tid + 256 * i;
        int k = idx >> 5, n = idx & 31;
        tile[k][n] = w1[((size_t)e * K + k0 + k) * N + n0 + n];
    }
    __syncthreads();
    int w = tid >> 5, l = tid & 31;
#pragma unroll
    for (int m = 0; m < 4; m++) {
        int n = w + 8 * m;
        float a = tile[2 * l][n], b = tile[2 * l + 1][n];
        __nv_bfloat16 ha = __float2bfloat16(a), hb = __float2bfloat16(b);
        __nv_bfloat162 hp; hp.x = ha; hp.y = hb;
        __nv_bfloat162 lp;
        lp.x = __float2bfloat16(a - __bfloat162float(ha));
        lp.y = __float2bfloat16(b - __bfloat162float(hb));
        size_t o = ((size_t)e * N + n0 + n) * K + k0 + 2 * l;
        *(__nv_bfloat162*)&g_w1hi[o] = hp;
        *(__nv_bfloat162*)&g_w1lo[o] = lp;
    }
}

// ===================== GEMM1: gate/up =======================================
// Block tile M=128 (gathered rows), N=64 F-cols (gate AND up).
// 8 warps = 4(m) x 2(n), warp tile 32x32. K-chunk 16, 3-stage cp.async.
// Dynamic smem = 49152 (48KB) exactly; NO static __shared__ in this kernel.
#define G1_AHI 0
#define G1_ALO 4096
#define G1_GH  8192
#define G1_GL  10240
#define G1_VH  12288
#define G1_VL  14336
#define G1_STAGE 16384
#define G1_SMEM (3 * G1_STAGE)
#define G1_NC 64            // 1024 / 16

__global__ void __launch_bounds__(256)
k_gemm1(const float* __restrict__ x) {
    int e = blockIdx.z;
    int cnt = g_cnt[e];
    int m0 = blockIdx.y * 128;
    if (m0 >= cnt) return;
    int n0 = blockIdx.x * 64;

    extern __shared__ char smem[];
    uint32_t sb32 = smem_to_u32(smem);
    int tid = threadIdx.x;
    int lane = tid & 31, wid = tid >> 5;
    int wm = wid & 3, wn = wid >> 2;
    int qr = lane >> 2, qc = (lane & 3) << 2;

    // ---- A loader: row = tid>>1, chunk-half = tid&1 (8 fp32 -> 16B bf16) ----
    int arow = tid >> 1, aq = tid & 1;
    int ar = m0 + arow;
    int atok = (ar < cnt) ? (g_list[e][ar] >> 1) : 0;    // clamp: rows discarded
    const float4* xs = (const float4*)x + (size_t)atok * (HH / 4) + aq * 2;
    int a_so = aoff(arow, aq);
    float4 ra0, ra1;

    // ---- B loader (cp.async): grp 0 -> gate mats, 1 -> up mats --------------
    int grp = tid >> 7, rem = tid & 127, br = rem >> 1, bcb = rem & 1;
    size_t bel = ((size_t)e * FF + n0 + br) * HH + bcb * 8;
    const char* bsrc1 = (const char*)((grp ? g_wvhi : g_wghi) + bel);
    const char* bsrc2 = (const char*)((grp ? g_wvlo : g_wglo) + bel);
    uint32_t bd1 = (grp ? G1_VH : G1_GH) + aoff(br, bcb);
    uint32_t bd2 = (grp ? G1_VL : G1_GL) + aoff(br, bcb);

    auto cpB = [&](int j, int st) {
        uint32_t s = sb32 + st * G1_STAGE;
        CP_ASYNC16(s + bd1, bsrc1 + j * 32);
        CP_ASYNC16(s + bd2, bsrc2 + j * 32);
    };
    auto loadA = [&](int j) { ra0 = xs[j * 4]; ra1 = xs[j * 4 + 1]; };
    auto storeA = [&](int st) {
        char* base = smem + st * G1_STAGE;
        uint4 h, l;
        h.x = pack_bf16(ra0.x, ra0.y); h.y = pack_bf16(ra0.z, ra0.w);
        h.z = pack_bf16(ra1.x, ra1.y); h.w = pack_bf16(ra1.z, ra1.w);
        l.x = pack_bf16(ra0.x - __bfloat162float(__float2bfloat16(ra0.x)),
                        ra0.y - __bfloat162float(__float2bfloat16(ra0.y)));
        l.y = pack_bf16(ra0.z - __bfloat162float(__float2bfloat16(ra0.z)),
                        ra0.w - __bfloat162float(__float2bfloat16(ra0.w)));
        l.z = pack_bf16(ra1.x - __bfloat162float(__float2bfloat16(ra1.x)),
                        ra1.y - __bfloat162float(__float2bfloat16(ra1.y)));
        l.w = pack_bf16(ra1.z - __bfloat162float(__float2bfloat16(ra1.z)),
                        ra1.w - __bfloat162float(__float2bfloat16(ra1.w)));
        *(uint4*)(base + G1_AHI + a_so) = h;
        *(uint4*)(base + G1_ALO + a_so) = l;
    };

    float accg[2][4][4], accu[2][4][4];
#pragma unroll
    for (int i = 0; i < 2; i++)
#pragma unroll
        for (int j = 0; j < 4; j++)
#pragma unroll
            for (int q = 0; q < 4; q++) { accg[i][j][q] = 0.f; accu[i][j][q] = 0.f; }

    auto compute = [&](int st) {
        const char* base = smem + st * G1_STAGE;
        uint32_t ah[2][4], al[2][4];
#pragma unroll
        for (int i = 0; i < 2; i++) {
            int r = wm * 32 + i * 16 + qr;
            const char* pH = base + G1_AHI;
            const char* pL = base + G1_ALO;
            ah[i][0] = *(const uint32_t*)(pH + aoff(r, 0) + qc);
            ah[i][1] = *(const uint32_t*)(pH + aoff(r + 8, 0) + qc);
            ah[i][2] = *(const uint32_t*)(pH + aoff(r, 1) + qc);
            ah[i][3] = *(const uint32_t*)(pH + aoff(r + 8, 1) + qc);
            al[i][0] = *(const uint32_t*)(pL + aoff(r, 0) + qc);
            al[i][1] = *(const uint32_t*)(pL + aoff(r + 8, 0) + qc);
            al[i][2] = *(const uint32_t*)(pL + aoff(r, 1) + qc);
            al[i][3] = *(const uint32_t*)(pL + aoff(r + 8, 1) + qc);
        }
#pragma unroll
        for (int j = 0; j < 4; j++) {
            int rb = wn * 32 + j * 8 + qr;
            uint32_t bgh[2], bgl[2], bvh[2], bvl[2];
            bgh[0] = *(const uint32_t*)(base + G1_GH + aoff(rb, 0) + qc);
            bgh[1] = *(const uint32_t*)(base + G1_GH + aoff(rb, 1) + qc);
            bgl[0] = *(const uint32_t*)(base + G1_GL + aoff(rb, 0) + qc);
            bgl[1] = *(const uint32_t*)(base + G1_GL + aoff(rb, 1) + qc);
            bvh[0] = *(const uint32_t*)(base + G1_VH + aoff(rb, 0) + qc);
            bvh[1] = *(const uint32_t*)(base + G1_VH + aoff(rb, 1) + qc);
            bvl[0] = *(const uint32_t*)(base + G1_VL + aoff(rb, 0) + qc);
            bvl[1] = *(const uint32_t*)(base + G1_VL + aoff(rb, 1) + qc);
#pragma unroll
            for (int i = 0; i < 2; i++) {
                mma_bf16(accg[i][j], ah[i], bgh);
                mma_bf16(accg[i][j], al[i], bgh);
                mma_bf16(accg[i][j], ah[i], bgl);
                mma_bf16(accu[i][j], ah[i], bvh);
                mma_bf16(accu[i][j], al[i], bvh);
                mma_bf16(accu[i][j], ah[i], bvl);
            }
        }
    };

    // ---- pipelined mainloop --------------------------------------------
    cpB(0, 0); CP_COMMIT();
    cpB(1, 1); CP_COMMIT();
    loadA(0); storeA(0);
    loadA(1);
#pragma unroll 1
    for (int j = 0; j < G1_NC; j++) {
        __syncthreads();                         // stage (j+2)%3 free to write
        if (j + 2 < G1_NC) cpB(j + 2, (j + 2) % 3);
        CP_COMMIT();
        storeA((j + 1) % 3);                     // A chunk j+1
        if (j + 2 < G1_NC) loadA(j + 2);
        CP_WAIT2();
        __syncthreads();
        compute(j % 3);
    }

    // ---- epilogue: gu = gelu_exact(gate) * up -> bf16 hi/lo -------------
    int c2 = (lane & 3) << 1;
#pragma unroll
    for (int i = 0; i < 2; i++) {
        int er0 = m0 + wm * 32 + i * 16 + qr;
        int er1 = er0 + 8;
        int gr0 = g_off[e] + er0, gr1 = g_off[e] + er1;
#pragma unroll
        for (int j = 0; j < 4; j++) {
            int col = n0 + wn * 32 + j * 8 + c2;
#pragma unroll
            for (int h = 0; h < 2; h++) {
                int er = h ? er1 : er0;
                if (er >= cnt) continue;
                int grow = h ? gr1 : gr0;
                float gx = accg[i][j][h * 2 + 0], gy = accg[i][j][h * 2 + 1];
                float ux = accu[i][j][h * 2 + 0], uy = accu[i][j][h * 2 + 1];
                float g0 = 0.5f * gx * (1.f + erff(gx * 0.70710678118654752f)) * ux;
                float g1 = 0.5f * gy * (1.f + erff(gy * 0.70710678118654752f)) * uy;
                __nv_bfloat16 h0 = __float2bfloat16(g0);
                __nv_bfloat16 h1 = __float2bfloat16(g1);
                __nv_bfloat162 hp; hp.x = h0; hp.y = h1;
                __nv_bfloat162 lp;
                lp.x = __float2bfloat16(g0 - __bfloat162float(h0));
                lp.y = __float2bfloat16(g1 - __bfloat162float(h1));
                size_t bo = (size_t)grow * FF + col;
                *reinterpret_cast<__nv_bfloat162*>(&g_guhi[bo]) = hp;
                *reinterpret_cast<__nv_bfloat162*>(&g_gulo[bo]) = lp;
            }
        }
    }
}

// ===================== GEMM2: down ==========================================
// Block tile M=128, N=64 H-cols. All operands via cp.async, 3 stages (36KB).
#define G2_AHI 0
#define G2_ALO 4096
#define G2_BH  8192
#define G2_BL  10240
#define G2_STAGE 12288
#define G2_SMEM (3 * G2_STAGE)
#define G2_NC 256           // 4096 / 16

__global__ void __launch_bounds__(256)
k_gemm2() {
    int e = blockIdx.z;
    int cnt = g_cnt[e];
    int m0 = blockIdx.y * 128;
    if (m0 >= cnt) return;
    int n0 = blockIdx.x * 64;

    extern __shared__ char smem[];
    uint32_t sb32 = smem_to_u32(smem);
    int tid = threadIdx.x;
    int lane = tid & 31, wid = tid >> 5;
    int wm = wid & 3, wn = wid >> 2;
    int qr = lane >> 2, qc = (lane & 3) << 2;

    int grow0 = g_off[e] + m0;     // contiguous A rows (buffer padded past end)

    // A: 2 ops/thread over {mat, row, chunk}
    int o0 = tid, o1 = tid + 256;
    int am0 = o0 >> 8, ar0 = (o0 & 255) >> 1, ac0 = o0 & 1;
    int am1 = o1 >> 8, ar1 = (o1 & 255) >> 1, ac1 = o1 & 1;
    const char* asrc0 = (const char*)((am0 ? g_gulo : g_guhi) +
                        ((size_t)(grow0 + ar0) * FF + ac0 * 8));
    const char* asrc1 = (const char*)((am1 ? g_gulo : g_guhi) +
                        ((size_t)(grow0 + ar1) * FF + ac1 * 8));
    uint32_t ad0 = (am0 ? G2_ALO : G2_AHI) + aoff(ar0, ac0);
    uint32_t ad1 = (am1 ? G2_ALO : G2_AHI) + aoff(ar1, ac1);
    // B: 1 op/thread
    int bm = tid >> 7, brr = (tid & 127) >> 1, bcb = tid & 1;
    const char* bsrc = (const char*)((bm ? g_w1lo : g_w1hi) +
                       (((size_t)e * HH + n0 + brr) * FF + bcb * 8));
    uint32_t bd = (bm ? G2_BL : G2_BH) + aoff(brr, bcb);

    auto cpAB = [&](int j, int st) {
        uint32_t s = sb32 + st * G2_STAGE;
        CP_ASYNC16(s + ad0, asrc0 + j * 32);
        CP_ASYNC16(s + ad1, asrc1 + j * 32);
        CP_ASYNC16(s + bd,  bsrc  + j * 32);
    };

    float acc[2][4][4];
#pragma unroll
    for (int i = 0; i < 2; i++)
#pragma unroll
        for (int j = 0; j < 4; j++)
#pragma unroll
            for (int q = 0; q < 4; q++) acc[i][j][q] = 0.f;

    auto compute = [&](int st) {
        const char* base = smem + st * G2_STAGE;
        uint32_t ah[2][4], al[2][4];
#pragma unroll
        for (int i = 0; i < 2; i++) {
            int r = wm * 32 + i * 16 + qr;
            const char* pH = base + G2_AHI;
            const char* pL = base + G2_ALO;
            ah[i][0] = *(const uint32_t*)(pH + aoff(r, 0) + qc);
            ah[i][1] = *(const uint32_t*)(pH + aoff(r + 8, 0) + qc);
            ah[i][2] = *(const uint32_t*)(pH + aoff(r, 1) + qc);
            ah[i][3] = *(const uint32_t*)(pH + aoff(r + 8, 1) + qc);
            al[i][0] = *(const uint32_t*)(pL + aoff(r, 0) + qc);
            al[i][1] = *(const uint32_t*)(pL + aoff(r + 8, 0) + qc);
            al[i][2] = *(const uint32_t*)(pL + aoff(r, 1) + qc);
            al[i][3] = *(const uint32_t*)(pL + aoff(r + 8, 1) + qc);
        }
#pragma unroll
        for (int j = 0; j < 4; j++) {
            int rb = wn * 32 + j * 8 + qr;
            uint32_t bh[2], bl[2];
            bh[0] = *(const uint32_t*)(base + G2_BH + aoff(rb, 0) + qc);
            bh[1] = *(const uint32_t*)(base + G2_BH + aoff(rb, 1) + qc);
            bl[0] = *(const uint32_t*)(base + G2_BL + aoff(rb, 0) + qc);
            bl[1] = *(const uint32_t*)(base + G2_BL + aoff(rb, 1) + qc);
#pragma unroll
            for (int i = 0; i < 2; i++) {
                mma_bf16(acc[i][j], ah[i], bh);
                mma_bf16(acc[i][j], al[i], bh);
                mma_bf16(acc[i][j], ah[i], bl);
            }
        }
    };

    cpAB(0, 0); CP_COMMIT();
    cpAB(1, 1); CP_COMMIT();
#pragma unroll 1
    for (int j = 0; j < G2_NC; j++) {
        __syncthreads();
        if (j + 2 < G2_NC) cpAB(j + 2, (j + 2) % 3);
        CP_COMMIT();
        CP_WAIT2();
        __syncthreads();
        compute(j % 3);
    }

    // epilogue: write w * acc into per-slot buffer
    int c2 = (lane & 3) << 1;
#pragma unroll
    for (int i = 0; i < 2; i++) {
        int er0 = m0 + wm * 32 + i * 16 + qr;
        int er1 = er0 + 8;
        int tok0 = 0, tok1 = 0, sl0 = 0, sl1 = 0; float w0 = 0.f, w1 = 0.f;
        if (er0 < cnt) { int ts = g_list[e][er0]; tok0 = ts >> 1; sl0 = ts & 1; w0 = g_rw[tok0][sl0]; }
        if (er1 < cnt) { int ts = g_list[e][er1]; tok1 = ts >> 1; sl1 = ts & 1; w1 = g_rw[tok1][sl1]; }
#pragma unroll
        for (int j = 0; j < 4; j++) {
            int col = n0 + wn * 32 + j * 8 + c2;
            if (er0 < cnt) {
                float* o = &g_dn[sl0][tok0][col];
                o[0] = w0 * acc[i][j][0];
                o[1] = w0 * acc[i][j][1];
            }
            if (er1 < cnt) {
                float* o = &g_dn[sl1][tok1][col];
                o[0] = w1 * acc[i][j][2];
                o[1] = w1 * acc[i][j][3];
            }
        }
    }
}

// ===================== combine ==============================================
__global__ void k_combine(float* __restrict__ out) {
    int i = blockIdx.x * blockDim.x + threadIdx.x;
    const float4* a = (const float4*)&g_dn[0][0][0];
    const float4* b = (const float4*)&g_dn[1][0][0];
    float4 u = a[i], v = b[i];
    ((float4*)out)[i] = make_float4(u.x + v.x, u.y + v.y, u.z + v.z, u.w + v.w);
}

// ===================== launch ==============================================
extern "C" void kernel_launch(void* const* d_in, const int* in_sizes, int n_in,
                              void* d_out, int out_size) {
    const float* x     = (const float*)d_in[0];
    const float* wgate = (const float*)d_in[1];
    const float* wg    = (const float*)d_in[2];
    const float* wv    = (const float*)d_in[3];
    const float* w1    = (const float*)d_in[4];
    float* out = (float*)d_out;

    k_conv_gv<<<dim3(FF / 32, HH / 64, EE * 2), 256>>>(wg, wv);      // 0
    k_conv_w1<<<dim3(HH / 32, FF / 64, EE), 256>>>(w1);              // 1
    k_init<<<1, 32>>>();                                             // 2
    k_router<<<TT, 128>>>(x, wgate, out + (size_t)TT * HH);          // 3
    k_prefix<<<1, 32>>>();                                           // 4
    k_gemm1<<<dim3(FF / 64, TT / 128, EE), 256, G1_SMEM>>>(x);       // 5 (ncu slot)
    k_gemm2<<<dim3(HH / 64, TT / 128, EE), 256, G2_SMEM>>>();        // 6
    k_combine<<<(TT * HH / 4) / 256, 256>>>(out);                    // 7
}